// round 4
// baseline (speedup 1.0000x reference)
#include <cuda_runtime.h>
#include <cstdint>

// ---------------- problem constants ----------------
#define L_      13689           // LH*LW
#define LPAD    13696           // 107 * 128
#define D_      3072            // C*KH*KW
#define NMEM    4096
#define HH      128
#define WW      128
#define CC      3
#define KHH     32
#define KWW     32
#define PADP    10
#define LHH     117
#define LWW     117

// ---------------- GEMM tiling ----------------
#define NSPLIT  8               // N-range splits -> 856 blocks
#define CHUNKS  4               // (4096 / NSPLIT) / 128
#define KB      16
#define NTILES  (D_ / KB)       // 192

typedef unsigned long long ull;

// ---------------- static device scratch (no allocation allowed) ----------------
__device__ float g_patchesT[(size_t)D_ * LPAD];   // ~168 MB, k-major patches
__device__ float g_memT[(size_t)D_ * NMEM];       // ~50 MB,  k-major mem
__device__ float g_bias[NMEM];                    // -0.5*||mem_n||^2
__device__ float g_partv[NSPLIT * LPAD];
__device__ int   g_partn[NSPLIT * LPAD];
__device__ int   g_pid[L_];
__device__ float g_facc[CC * HH * WW];            // folded image (C,H,W)
__device__ unsigned int g_maxkey;

// ---------------- cp.async helpers ----------------
__device__ __forceinline__ void cp16(void* smem_dst, const void* gsrc) {
    unsigned saddr = (unsigned)__cvta_generic_to_shared(smem_dst);
    asm volatile("cp.async.cg.shared.global [%0], [%1], 16;" :: "r"(saddr), "l"(gsrc));
}
__device__ __forceinline__ void cp_commit() {
    asm volatile("cp.async.commit_group;");
}
template <int N>
__device__ __forceinline__ void cp_wait() {
    asm volatile("cp.async.wait_group %0;" :: "n"(N));
}

// ---------------- kernel 1: bias = -0.5 * ||mem_n||^2 ----------------
__global__ void k_bias(const float* __restrict__ mem) {
    int row = blockIdx.x;
    const float* r = mem + (size_t)row * D_;
    float s = 0.f;
    for (int i = threadIdx.x; i < D_; i += 128) { float v = r[i]; s += v * v; }
#pragma unroll
    for (int o = 16; o; o >>= 1) s += __shfl_xor_sync(0xffffffffu, s, o);
    __shared__ float ws[4];
    if ((threadIdx.x & 31) == 0) ws[threadIdx.x >> 5] = s;
    __syncthreads();
    if (threadIdx.x == 0) g_bias[row] = -0.5f * (ws[0] + ws[1] + ws[2] + ws[3]);
}

// ---------------- kernel 2: memT[d][n] = mem[n][d] ----------------
__global__ void k_transpose(const float* __restrict__ mem) {
    __shared__ float tile[32][33];
    int x = blockIdx.x * 32 + threadIdx.x;   // d
    int y0 = blockIdx.y * 32;                // n
#pragma unroll
    for (int j = 0; j < 32; j += 8)
        tile[threadIdx.y + j][threadIdx.x] = mem[(size_t)(y0 + threadIdx.y + j) * D_ + x];
    __syncthreads();
    int n  = y0 + threadIdx.x;
    int d0 = blockIdx.x * 32;
#pragma unroll
    for (int j = 0; j < 32; j += 8)
        g_memT[(size_t)(d0 + threadIdx.y + j) * NMEM + n] = tile[threadIdx.x][threadIdx.y + j];
}

// ---------------- kernel 3: im2col (transposed) ----------------
// patchesT[d][l] = padded_image[c, lh+kh, lw+kw], d = c*1024 + kh*32 + kw
__global__ void k_im2col(const float* __restrict__ image) {
    int l = blockIdx.x * 128 + threadIdx.x;  // < LPAD
    int d = blockIdx.y;
    float v = 0.f;
    if (l < L_) {
        int lh = l / LWW, lw = l - lh * LWW;
        int c  = d >> 10;
        int kh = (d >> 5) & 31;
        int kw = d & 31;
        int y = lh + kh - PADP, x = lw + kw - PADP;
        if ((unsigned)y < HH && (unsigned)x < WW)
            v = image[(y * WW + x) * CC + c];
    }
    g_patchesT[(size_t)d * LPAD + l] = v;
}

// ---------------- kernel 4: fused GEMM + argmax ----------------
// block: 128 L-rows x (512 N-cols, in 4 chunks of 128). 256 threads, 8x8 micro-tile
// packed as 8 rows x 4 f32x2-column-pairs. Exact fp32 accumulation (per-lane FFMA chain).
__global__ __launch_bounds__(256, 2) void k_gemm() {
    __shared__ float sm[8192];               // 32 KB: As[2][16][128] | Bs[2][16][128]
    float* As = sm;
    float* Bs = sm + 4096;

    const int tid = threadIdx.x;
    const int tx = tid & 15, ty = tid >> 4;
    const int rowBase = blockIdx.x * 128;
    const int split   = blockIdx.y;

    float bestv[8];
    int   bestn[8];
#pragma unroll
    for (int i = 0; i < 8; ++i) { bestv[i] = -3.0e38f; bestn[i] = 0; }

    for (int chunk = 0; chunk < CHUNKS; ++chunk) {
        const int nBase = split * (NMEM / NSPLIT) + chunk * 128;

        ull acc[8][4];
#pragma unroll
        for (int i = 0; i < 8; ++i)
#pragma unroll
            for (int j = 0; j < 4; ++j) acc[i][j] = 0ull;

        // stage tile 0 into buf 0
        {
#pragma unroll
            for (int r = 0; r < 2; ++r) {
                int idx = tid + r * 256;     // 0..511
                int k = idx >> 5;            // 0..15
                int q = idx & 31;            // 0..31 (float4 within 128)
                cp16(&As[k * 128 + q * 4], &g_patchesT[(size_t)k * LPAD + rowBase + q * 4]);
                cp16(&Bs[k * 128 + q * 4], &g_memT[(size_t)k * NMEM + nBase + q * 4]);
            }
            cp_commit();
        }

        int buf = 0;
        for (int t = 0; t < NTILES; ++t) {
            if (t + 1 < NTILES) {
                const int kb = (t + 1) * KB;
                float* Ad = As + (buf ^ 1) * 2048;
                float* Bd = Bs + (buf ^ 1) * 2048;
#pragma unroll
                for (int r = 0; r < 2; ++r) {
                    int idx = tid + r * 256;
                    int k = idx >> 5;
                    int q = idx & 31;
                    cp16(&Ad[k * 128 + q * 4], &g_patchesT[(size_t)(kb + k) * LPAD + rowBase + q * 4]);
                    cp16(&Bd[k * 128 + q * 4], &g_memT[(size_t)(kb + k) * NMEM + nBase + q * 4]);
                }
                cp_commit();
                cp_wait<1>();                // current tile's group complete
            } else {
                cp_wait<0>();
            }
            __syncthreads();

            const float* Ac = As + buf * 2048;
            const float* Bc = Bs + buf * 2048;
#pragma unroll
            for (int k = 0; k < KB; ++k) {
                float4 a0 = *(const float4*)(Ac + k * 128 + ty * 8);
                float4 a1 = *(const float4*)(Ac + k * 128 + ty * 8 + 4);
                ulonglong2 b0 = *(const ulonglong2*)(Bc + k * 128 + tx * 8);
                ulonglong2 b1 = *(const ulonglong2*)(Bc + k * 128 + tx * 8 + 4);
                ull bp0 = b0.x, bp1 = b0.y, bp2 = b1.x, bp3 = b1.y;
                float av[8] = {a0.x, a0.y, a0.z, a0.w, a1.x, a1.y, a1.z, a1.w};
#pragma unroll
                for (int i = 0; i < 8; ++i) {
                    ull ap;
                    asm("mov.b64 %0, {%1, %1};" : "=l"(ap) : "r"(__float_as_uint(av[i])));
                    asm("fma.rn.f32x2 %0, %1, %2, %0;" : "+l"(acc[i][0]) : "l"(ap), "l"(bp0));
                    asm("fma.rn.f32x2 %0, %1, %2, %0;" : "+l"(acc[i][1]) : "l"(ap), "l"(bp1));
                    asm("fma.rn.f32x2 %0, %1, %2, %0;" : "+l"(acc[i][2]) : "l"(ap), "l"(bp2));
                    asm("fma.rn.f32x2 %0, %1, %2, %0;" : "+l"(acc[i][3]) : "l"(ap), "l"(bp3));
                }
            }
            __syncthreads();
            buf ^= 1;
        }

        // epilogue: add bias, update running argmax (n ascending -> first-max wins)
#pragma unroll
        for (int i = 0; i < 8; ++i) {
#pragma unroll
            for (int j = 0; j < 4; ++j) {
                float s0 = __uint_as_float((unsigned)(acc[i][j] & 0xffffffffull));
                float s1 = __uint_as_float((unsigned)(acc[i][j] >> 32));
                int n0 = nBase + tx * 8 + j * 2;
                s0 += g_bias[n0];
                s1 += g_bias[n0 + 1];
                if (s0 > bestv[i]) { bestv[i] = s0; bestn[i] = n0; }
                if (s1 > bestv[i]) { bestv[i] = s1; bestn[i] = n0 + 1; }
            }
        }
    }

    // cross-thread (16 tx) reduction per row, tie-break lower n
    __syncthreads();
    float* rv = sm;                          // 128*16 floats
    int*   rn = (int*)(sm + 2048);           // 128*16 ints
#pragma unroll
    for (int i = 0; i < 8; ++i) {
        int row = ty * 8 + i;
        rv[row * 16 + tx] = bestv[i];
        rn[row * 16 + tx] = bestn[i];
    }
    __syncthreads();
    if (tid < 128) {
        float bv = rv[tid * 16];
        int   bn = rn[tid * 16];
#pragma unroll
        for (int j = 1; j < 16; ++j) {
            float v = rv[tid * 16 + j];
            int   n = rn[tid * 16 + j];
            if (v > bv || (v == bv && n < bn)) { bv = v; bn = n; }
        }
        g_partv[split * LPAD + rowBase + tid] = bv;
        g_partn[split * LPAD + rowBase + tid] = bn;
    }
}

// ---------------- kernel 5: combine splits, map to pattern ids ----------------
__global__ void k_combine(const int* __restrict__ mapping) {
    int l = blockIdx.x * 256 + threadIdx.x;
    if (l == 0) g_maxkey = 0u;               // reset for fold's atomicMax
    if (l >= L_) return;
    float bv = g_partv[l];
    int   bn = g_partn[l];
#pragma unroll
    for (int s = 1; s < NSPLIT; ++s) {
        float v = g_partv[s * LPAD + l];
        int   n = g_partn[s * LPAD + l];
        if (v > bv || (v == bv && n < bn)) { bv = v; bn = n; }
    }
    g_pid[l] = mapping[bn];
}

// ---------------- kernel 6: fold (gather) + global max ----------------
__global__ void k_fold(const float* __restrict__ mem2) {
    __shared__ int spid[32 * LWW];           // up to 32 lh rows of pattern ids
    const int h = blockIdx.x;
    const int c = blockIdx.y;
    const int w = threadIdx.x;               // 0..127

    const int lh0 = max(0, h - (KHH - 1 - PADP));   // h - 21
    const int lh1 = min(LHH - 1, h + PADP);         // h + 10
    const int nrows = lh1 - lh0 + 1;
    for (int idx = threadIdx.x; idx < nrows * LWW; idx += 128)
        spid[idx] = g_pid[(lh0 + idx / LWW) * LWW + idx % LWW];
    __syncthreads();

    float s = 0.f;
#pragma unroll 1
    for (int kh = 0; kh < KHH; ++kh) {
        int lh = h + PADP - kh;
        if (lh < lh0 || lh > lh1) continue;
        const int base = (lh - lh0) * LWW;
        const int rowoff = c * 1024 + kh * 32;
#pragma unroll
        for (int kw = 0; kw < KWW; ++kw) {
            int lw = w + PADP - kw;
            if ((unsigned)lw < LWW) {
                int pid = spid[base + lw];
                s += __ldg(&mem2[(size_t)pid * D_ + rowoff + kw]);
            }
        }
    }
    g_facc[(c * HH + h) * WW + w] = s;

    // block max -> global atomic max via order-preserving uint key
    float m = s;
#pragma unroll
    for (int o = 16; o; o >>= 1) m = fmaxf(m, __shfl_xor_sync(0xffffffffu, m, o));
    __shared__ float wm[4];
    if ((threadIdx.x & 31) == 0) wm[threadIdx.x >> 5] = m;
    __syncthreads();
    if (threadIdx.x == 0) {
        m = fmaxf(fmaxf(wm[0], wm[1]), fmaxf(wm[2], wm[3]));
        unsigned b = __float_as_uint(m);
        unsigned key = (b & 0x80000000u) ? ~b : (b | 0x80000000u);
        atomicMax(&g_maxkey, key);
    }
}

// ---------------- kernel 7: normalize + transpose to (H,W,C) ----------------
__global__ void k_norm(float* __restrict__ out) {
    int i = blockIdx.x * 256 + threadIdx.x;
    if (i >= HH * WW * CC) return;
    unsigned key = g_maxkey;
    unsigned b = (key & 0x80000000u) ? (key & 0x7fffffffu) : ~key;
    float mx = __uint_as_float(b);
    int c = i % CC;
    int w = (i / CC) % WW;
    int h = i / (CC * WW);
    out[i] = g_facc[(c * HH + h) * WW + w] / mx;
}

// ---------------- launcher ----------------
extern "C" void kernel_launch(void* const* d_in, const int* in_sizes, int n_in,
                              void* d_out, int out_size) {
    const float* image   = (const float*)d_in[0];
    const float* mem     = (const float*)d_in[1];
    const float* mem2    = (const float*)d_in[2];
    const int*   mapping = (const int*)d_in[3];
    float* out = (float*)d_out;

    k_bias<<<NMEM, 128>>>(mem);
    k_transpose<<<dim3(D_ / 32, NMEM / 32), dim3(32, 8)>>>(mem);
    k_im2col<<<dim3(LPAD / 128, D_), 128>>>(image);
    k_gemm<<<dim3(LPAD / 128, NSPLIT), 256>>>();
    k_combine<<<(L_ + 255) / 256, 256>>>(mapping);
    k_fold<<<dim3(HH, CC), 128>>>(mem2);
    k_norm<<<(HH * WW * CC + 255) / 256, 256>>>(out);
}

// round 7
// speedup vs baseline: 4.2911x; 4.2911x over previous
#include <cuda_runtime.h>
#include <cuda_bf16.h>
#include <cstdint>

// ---------------- problem constants ----------------
#define L_      13689           // LH*LW
#define LPAD    13696           // 107 * 128
#define D_      3072            // C*KH*KW
#define NMEM    4096
#define HH      128
#define WW      128
#define CC      3
#define KHH     32
#define KWW     32
#define PADP    10
#define LHH     117
#define LWW     117

// ---------------- GEMM tiling (mma.sync bf16, m16n8k16) ----------------
#define TM      128
#define TN      256
#define TK      32
#define NKT     (D_ / TK)        // 96
#define AROW    80               // bytes per smem row: 32 bf16 (64B) + 16B pad
#define ASTG    (TM * AROW)      // 10240
#define BSTG    (TN * AROW)      // 20480
#define STG     (ASTG + BSTG)    // 30720
#define SMEM_GEMM (4 * STG)      // 122880 (4 stages)

#define MARGIN  2.0f
#define CMAX    16

typedef unsigned long long ull;

// ---------------- static device scratch ----------------
__device__ __align__(16) float         g_Af32[(size_t)LPAD * D_];   // 168 MB exact patches
__device__ __align__(16) __nv_bfloat16 g_Abf [(size_t)LPAD * D_];   // 84 MB
__device__ __align__(16) __nv_bfloat16 g_Bbf [(size_t)NMEM * D_];   // 25 MB
__device__ __align__(16) float         g_bias[NMEM];                // -0.5*||mem_n||^2 exact
__device__ __align__(16) float         g_scores[(size_t)LPAD * NMEM]; // 224 MB
__device__ int   g_cand[(size_t)L_ * CMAX];
__device__ int   g_candcnt[L_];
__device__ int   g_pid[L_];
__device__ float g_facc[CC * HH * WW];
__device__ unsigned int g_maxkey;

// ---------------- helpers ----------------
__device__ __forceinline__ uint32_t smem_u32(const void* p) {
    uint32_t a;
    asm("{ .reg .u64 t; cvta.to.shared.u64 t, %1; cvt.u32.u64 %0, t; }" : "=r"(a) : "l"(p));
    return a;
}
__device__ __forceinline__ void cp16(uint32_t smem_dst, const void* gsrc) {
    asm volatile("cp.async.cg.shared.global [%0], [%1], 16;" :: "r"(smem_dst), "l"(gsrc));
}
__device__ __forceinline__ void cp_commit() { asm volatile("cp.async.commit_group;"); }
template <int N> __device__ __forceinline__ void cp_wait() {
    asm volatile("cp.async.wait_group %0;" :: "n"(N));
}

// ---------------- kernel 1: bias = -0.5 * ||mem_n||^2 (exact fp32) ----------------
__global__ void k_bias(const float* __restrict__ mem) {
    int row = blockIdx.x;
    const float* r = mem + (size_t)row * D_;
    float s = 0.f;
    for (int i = threadIdx.x; i < D_; i += 128) { float v = r[i]; s += v * v; }
#pragma unroll
    for (int o = 16; o; o >>= 1) s += __shfl_xor_sync(0xffffffffu, s, o);
    __shared__ float ws[4];
    if ((threadIdx.x & 31) == 0) ws[threadIdx.x >> 5] = s;
    __syncthreads();
    if (threadIdx.x == 0) g_bias[row] = -0.5f * (ws[0] + ws[1] + ws[2] + ws[3]);
}

// ---------------- kernel 2: mem -> bf16 ----------------
__global__ void k_convB(const float* __restrict__ mem) {
    size_t i = (size_t)blockIdx.x * 256 + threadIdx.x;
    g_Bbf[i] = __float2bfloat16(mem[i]);
}

// ---------------- kernel 3: im2col -> fp32 (exact) + bf16, layout [l][d] ----------------
__global__ void k_im2colA(const float* __restrict__ image) {
    const int l = blockIdx.x;                  // 0..LPAD-1
    const bool valid = l < L_;
    const int lh = l / LWW, lw = l - lh * LWW;
    float* a32 = g_Af32 + (size_t)l * D_;
    __nv_bfloat16* abf = g_Abf + (size_t)l * D_;
    for (int d = threadIdx.x; d < D_; d += 256) {
        float v = 0.f;
        if (valid) {
            int c = d >> 10, kh = (d >> 5) & 31, kw = d & 31;
            int y = lh + kh - PADP, x = lw + kw - PADP;
            if ((unsigned)y < HH && (unsigned)x < WW)
                v = image[(y * WW + x) * CC + c];
        }
        a32[d] = v;
        abf[d] = __float2bfloat16(v);
    }
}

// ---------------- kernel 4: bf16 mma.sync GEMM -> scores ----------------
// CTA 128x256, 512 threads, warps 4(M)x4(N), warp tile 32x64. 4-stage cp.async.
__global__ __launch_bounds__(512, 1) void k_gemm() {
    extern __shared__ char smem[];
    const uint32_t sb = smem_u32(smem);
    const int tid = threadIdx.x, lane = tid & 31, wid = tid >> 5;
    const int wm = (wid & 3) * 32, wn = (wid >> 2) * 64;
    const int rowBase = blockIdx.x * TM, nBase = blockIdx.y * TN;

    float acc[2][8][4];
#pragma unroll
    for (int mi = 0; mi < 2; ++mi)
#pragma unroll
        for (int nj = 0; nj < 8; ++nj)
#pragma unroll
            for (int q = 0; q < 4; ++q) acc[mi][nj][q] = 0.f;

    // stage loader: A 128x(32 bf16), B 256x(32 bf16); rows padded to 80B
    auto load_stage = [&](int kt) {
        const int slot = kt & 3;
        const uint32_t a0 = sb + slot * STG;
        const uint32_t b0 = a0 + ASTG;
        const int k0 = kt * TK;
        {   // A: one 16B chunk per thread (512 = 128 rows * 4 chunks)
            int r = tid >> 2, c = tid & 3;
            cp16(a0 + r * AROW + c * 16,
                 (const char*)g_Abf + ((size_t)(rowBase + r) * D_ + k0) * 2 + c * 16);
        }
#pragma unroll
        for (int i = 0; i < 2; ++i) {   // B: 1024 chunks
            int idx = tid + i * 512;
            int r = idx >> 2, c = idx & 3;
            cp16(b0 + r * AROW + c * 16,
                 (const char*)g_Bbf + ((size_t)(nBase + r) * D_ + k0) * 2 + c * 16);
        }
    };

    load_stage(0); cp_commit();
    load_stage(1); cp_commit();
    load_stage(2); cp_commit();

    for (int kt = 0; kt < NKT; ++kt) {
        cp_wait<2>();            // this thread's stage kt arrived
        __syncthreads();         // publish to all warps; all done with stage kt-1
        if (kt + 3 < NKT) load_stage(kt + 3);
        cp_commit();             // always commit (possibly empty) to keep counts uniform

        const uint32_t a0 = sb + (kt & 3) * STG;
        const uint32_t b0 = a0 + ASTG;
#pragma unroll
        for (int kh = 0; kh < 2; ++kh) {   // two k16 slices
            uint32_t af[2][4];
#pragma unroll
            for (int mi = 0; mi < 2; ++mi) {
                uint32_t addr = a0 + (wm + mi * 16 + (lane & 15)) * AROW
                              + kh * 32 + ((lane >> 4) & 1) * 16;
                asm volatile("ldmatrix.sync.aligned.m8n8.x4.shared.b16 {%0,%1,%2,%3}, [%4];"
                    : "=r"(af[mi][0]), "=r"(af[mi][1]), "=r"(af[mi][2]), "=r"(af[mi][3])
                    : "r"(addr));
            }
            // B tile is n-major (k contiguous) == same fragment layout as A:
            // non-trans ldmatrix; r0=(n0-7,kLo) r1=(n8-15,kLo) r2=(n0-7,kHi) r3=(n8-15,kHi)
            uint32_t bfr[8][2];
#pragma unroll
            for (int ni = 0; ni < 4; ++ni) {
                uint32_t r0, r1, r2, r3;
                uint32_t addr = b0 + (wn + ni * 16 + (lane & 15)) * AROW
                              + kh * 32 + ((lane >> 4) & 1) * 16;
                asm volatile("ldmatrix.sync.aligned.m8n8.x4.shared.b16 {%0,%1,%2,%3}, [%4];"
                    : "=r"(r0), "=r"(r1), "=r"(r2), "=r"(r3) : "r"(addr));
                bfr[ni * 2][0]     = r0; bfr[ni * 2][1]     = r2;   // n 0-7 of block
                bfr[ni * 2 + 1][0] = r1; bfr[ni * 2 + 1][1] = r3;   // n 8-15
            }
#pragma unroll
            for (int mi = 0; mi < 2; ++mi)
#pragma unroll
                for (int nj = 0; nj < 8; ++nj) {
                    asm volatile(
                        "mma.sync.aligned.m16n8k16.row.col.f32.bf16.bf16.f32 "
                        "{%0,%1,%2,%3}, {%4,%5,%6,%7}, {%8,%9}, {%0,%1,%2,%3};"
                        : "+f"(acc[mi][nj][0]), "+f"(acc[mi][nj][1]),
                          "+f"(acc[mi][nj][2]), "+f"(acc[mi][nj][3])
                        : "r"(af[mi][0]), "r"(af[mi][1]), "r"(af[mi][2]), "r"(af[mi][3]),
                          "r"(bfr[nj][0]), "r"(bfr[nj][1]));
                }
        }
    }

    // epilogue: score = acc + bias[n] -> g_scores
#pragma unroll
    for (int mi = 0; mi < 2; ++mi) {
        const int row0 = rowBase + wm + mi * 16 + (lane >> 2);
#pragma unroll
        for (int nj = 0; nj < 8; ++nj) {
            const int col = nBase + wn + nj * 8 + (lane & 3) * 2;
            float2 bv = *(const float2*)(g_bias + col);
            float2 s0 = make_float2(acc[mi][nj][0] + bv.x, acc[mi][nj][1] + bv.y);
            float2 s1 = make_float2(acc[mi][nj][2] + bv.x, acc[mi][nj][3] + bv.y);
            *(float2*)(g_scores + (size_t)row0 * NMEM + col) = s0;
            *(float2*)(g_scores + (size_t)(row0 + 8) * NMEM + col) = s1;
        }
    }
}

// ---------------- kernel 5: scan scores, decide or collect candidates ----------------
__global__ void k_select(const int* __restrict__ mapping) {
    if (blockIdx.x == 0 && threadIdx.x == 0) g_maxkey = 0u;   // reset for fold
    const int l = (blockIdx.x * blockDim.x + threadIdx.x) >> 5;
    const int lane = threadIdx.x & 31;
    if (l >= L_) return;
    const float* row = g_scores + (size_t)l * NMEM;

    float m1 = -3.4e38f, m2 = -3.4e38f;
    int i1 = 0;
    for (int n = lane; n < NMEM; n += 32) {
        float v = row[n];
        if (v > m1) { m2 = m1; m1 = v; i1 = n; }
        else if (v > m2) m2 = v;
    }
#pragma unroll
    for (int off = 16; off; off >>= 1) {
        float om1 = __shfl_xor_sync(0xffffffffu, m1, off);
        float om2 = __shfl_xor_sync(0xffffffffu, m2, off);
        int   oi1 = __shfl_xor_sync(0xffffffffu, i1, off);
        float c2 = fmaxf(fmaxf(m2, om2), fminf(m1, om1));
        if (om1 > m1 || (om1 == m1 && oi1 < i1)) { m1 = om1; i1 = oi1; }
        m2 = c2;
    }

    if (m1 - m2 > MARGIN) {
        if (lane == 0) { g_pid[l] = mapping[i1]; g_candcnt[l] = 1; }
        return;
    }
    // collect candidates within MARGIN of bf16 max (ascending n)
    const float thr = m1 - MARGIN;
    int base = 0;
    for (int n0 = 0; n0 < NMEM; n0 += 32) {
        float v = row[n0 + lane];
        bool p = v >= thr;
        unsigned mask = __ballot_sync(0xffffffffu, p);
        if (p) {
            int pos = base + __popc(mask & ((1u << lane) - 1u));
            if (pos < CMAX) g_cand[(size_t)l * CMAX + pos] = n0 + lane;
        }
        base += __popc(mask);
    }
    if (lane == 0) g_candcnt[l] = base;   // may exceed CMAX -> full rescan
}

// ---------------- kernel 6: exact fp32 rescue for ambiguous patches ----------------
__global__ void k_rescore(const float* __restrict__ mem, const int* __restrict__ mapping) {
    const int l = blockIdx.x;
    const int cnt = g_candcnt[l];
    if (cnt <= 1) return;

    __shared__ float sp[D_];     // 12 KB patch row
    __shared__ float red[4];
    const float* prow = g_Af32 + (size_t)l * D_;
    for (int k = threadIdx.x; k < D_; k += 128) sp[k] = prow[k];
    __syncthreads();

    const bool full = cnt > CMAX;
    const int num = full ? NMEM : cnt;
    float best = -3.4e38f;
    int bestn = 0;
    for (int c = 0; c < num; ++c) {
        const int n = full ? c : g_cand[(size_t)l * CMAX + c];
        const float* mrow = mem + (size_t)n * D_;
        float s = 0.f;
        for (int k = threadIdx.x; k < D_; k += 128) s = fmaf(sp[k], mrow[k], s);
#pragma unroll
        for (int o = 16; o; o >>= 1) s += __shfl_xor_sync(0xffffffffu, s, o);
        if ((threadIdx.x & 31) == 0) red[threadIdx.x >> 5] = s;
        __syncthreads();
        if (threadIdx.x == 0) {
            float tot = red[0] + red[1] + red[2] + red[3] + g_bias[n];
            if (tot > best) { best = tot; bestn = n; }   // ascending n -> first max wins
        }
        __syncthreads();
    }
    if (threadIdx.x == 0) g_pid[l] = mapping[bestn];
}

// ---------------- kernel 7: fold (gather) + global max ----------------
__global__ void k_fold(const float* __restrict__ mem2) {
    __shared__ int spid[32 * LWW];
    const int h = blockIdx.x;
    const int c = blockIdx.y;
    const int w = threadIdx.x;               // 0..127

    const int lh0 = max(0, h - (KHH - 1 - PADP));
    const int lh1 = min(LHH - 1, h + PADP);
    const int nrows = lh1 - lh0 + 1;
    for (int idx = threadIdx.x; idx < nrows * LWW; idx += 128)
        spid[idx] = g_pid[(lh0 + idx / LWW) * LWW + idx % LWW];
    __syncthreads();

    float s = 0.f;
#pragma unroll 1
    for (int kh = 0; kh < KHH; ++kh) {
        int lh = h + PADP - kh;
        if (lh < lh0 || lh > lh1) continue;
        const int base = (lh - lh0) * LWW;
        const int rowoff = c * 1024 + kh * 32;
#pragma unroll
        for (int kw = 0; kw < KWW; ++kw) {
            int lw = w + PADP - kw;
            if ((unsigned)lw < LWW) {
                int pid = spid[base + lw];
                s += __ldg(&mem2[(size_t)pid * D_ + rowoff + kw]);
            }
        }
    }
    g_facc[(c * HH + h) * WW + w] = s;

    float m = s;
#pragma unroll
    for (int o = 16; o; o >>= 1) m = fmaxf(m, __shfl_xor_sync(0xffffffffu, m, o));
    __shared__ float wm[4];
    if ((threadIdx.x & 31) == 0) wm[threadIdx.x >> 5] = m;
    __syncthreads();
    if (threadIdx.x == 0) {
        m = fmaxf(fmaxf(wm[0], wm[1]), fmaxf(wm[2], wm[3]));
        unsigned b = __float_as_uint(m);
        unsigned key = (b & 0x80000000u) ? ~b : (b | 0x80000000u);
        atomicMax(&g_maxkey, key);
    }
}

// ---------------- kernel 8: normalize + transpose to (H,W,C) ----------------
__global__ void k_norm(float* __restrict__ out) {
    int i = blockIdx.x * 256 + threadIdx.x;
    if (i >= HH * WW * CC) return;
    unsigned key = g_maxkey;
    unsigned b = (key & 0x80000000u) ? (key & 0x7fffffffu) : ~key;
    float mx = __uint_as_float(b);
    int c = i % CC;
    int w = (i / CC) % WW;
    int h = i / (CC * WW);
    out[i] = g_facc[(c * HH + h) * WW + w] / mx;
}

// ---------------- launcher ----------------
extern "C" void kernel_launch(void* const* d_in, const int* in_sizes, int n_in,
                              void* d_out, int out_size) {
    const float* image   = (const float*)d_in[0];
    const float* mem     = (const float*)d_in[1];
    const float* mem2    = (const float*)d_in[2];
    const int*   mapping = (const int*)d_in[3];
    float* out = (float*)d_out;

    cudaFuncSetAttribute(k_gemm, cudaFuncAttributeMaxDynamicSharedMemorySize, SMEM_GEMM);

    k_bias<<<NMEM, 128>>>(mem);
    k_convB<<<(NMEM * D_) / 256, 256>>>(mem);
    k_im2colA<<<LPAD, 256>>>(image);
    k_gemm<<<dim3(LPAD / TM, NMEM / TN), 512, SMEM_GEMM>>>();
    k_select<<<(L_ + 7) / 8, 256>>>(mapping);
    k_rescore<<<L_, 128>>>(mem, mapping);
    k_fold<<<dim3(HH, CC), 128>>>(mem2);
    k_norm<<<(HH * WW * CC + 255) / 256, 256>>>(out);
}

// round 8
// speedup vs baseline: 4.6459x; 1.0827x over previous
#include <cuda_runtime.h>
#include <cuda_bf16.h>
#include <cstdint>

// ---------------- problem constants ----------------
#define L_      13689           // LH*LW
#define LPAD    13696           // 107 * 128
#define D_      3072            // C*KH*KW
#define NMEM    4096
#define HH      128
#define WW      128
#define CC      3
#define KHH     32
#define KWW     32
#define PADP    10
#define LHH     117
#define LWW     117

// ---------------- GEMM tiling (mma.sync bf16, m16n8k16) ----------------
#define TM      128              // CTA M
#define TNB     128              // CTA N
#define TK      32
#define NKT     (D_ / TK)        // 96
#define AROW    80               // bytes per smem row: 32 bf16 (64B) + 16B pad
#define ASTG    (TM * AROW)      // 10240
#define BSTG    (TNB * AROW)     // 10240
#define STG     (ASTG + BSTG)    // 20480
#define SMEM_GEMM (4 * STG)      // 81920 (4 stages) -> 2 CTAs/SM

#define MARGIN  2.0f
#define CMAX    16

typedef unsigned long long ull;

// ---------------- static device scratch ----------------
__device__ __align__(16) float         g_Af32[(size_t)LPAD * D_];   // 168 MB exact patches
__device__ __align__(16) __nv_bfloat16 g_Abf [(size_t)LPAD * D_];   // 84 MB
__device__ __align__(16) __nv_bfloat16 g_Bbf [(size_t)NMEM * D_];   // 25 MB
__device__ __align__(16) float         g_bias[NMEM];                // -0.5*||mem_n||^2 exact
__device__ __align__(16) float         g_scores[(size_t)LPAD * NMEM]; // 224 MB
__device__ int   g_cand[(size_t)L_ * CMAX];
__device__ int   g_candcnt[L_];
__device__ int   g_pid[L_];
__device__ float g_facc[CC * HH * WW];
__device__ unsigned int g_maxkey;

// ---------------- helpers ----------------
__device__ __forceinline__ uint32_t smem_u32(const void* p) {
    uint32_t a;
    asm("{ .reg .u64 t; cvta.to.shared.u64 t, %1; cvt.u32.u64 %0, t; }" : "=r"(a) : "l"(p));
    return a;
}
__device__ __forceinline__ void cp16(uint32_t smem_dst, const void* gsrc) {
    asm volatile("cp.async.cg.shared.global [%0], [%1], 16;" :: "r"(smem_dst), "l"(gsrc));
}
__device__ __forceinline__ void cp_commit() { asm volatile("cp.async.commit_group;"); }
template <int N> __device__ __forceinline__ void cp_wait() {
    asm volatile("cp.async.wait_group %0;" :: "n"(N));
}

// ---------------- kernel 1: bias (exact fp32) + mem -> bf16 ----------------
__global__ void k_prepB(const float* __restrict__ mem) {
    int row = blockIdx.x;
    const float* r = mem + (size_t)row * D_;
    __nv_bfloat16* b = g_Bbf + (size_t)row * D_;
    float s = 0.f;
    for (int i = threadIdx.x; i < D_; i += 128) {
        float v = r[i];
        b[i] = __float2bfloat16(v);
        s += v * v;
    }
#pragma unroll
    for (int o = 16; o; o >>= 1) s += __shfl_xor_sync(0xffffffffu, s, o);
    __shared__ float ws[4];
    if ((threadIdx.x & 31) == 0) ws[threadIdx.x >> 5] = s;
    __syncthreads();
    if (threadIdx.x == 0) g_bias[row] = -0.5f * (ws[0] + ws[1] + ws[2] + ws[3]);
}

// ---------------- kernel 2: im2col -> fp32 (exact) + bf16, layout [l][d] ----------------
__global__ void k_im2colA(const float* __restrict__ image) {
    const int l = blockIdx.x;                  // 0..LPAD-1
    const bool valid = l < L_;
    const int lh = l / LWW, lw = l - lh * LWW;
    float* a32 = g_Af32 + (size_t)l * D_;
    __nv_bfloat16* abf = g_Abf + (size_t)l * D_;
    for (int d = threadIdx.x; d < D_; d += 256) {
        float v = 0.f;
        if (valid) {
            int c = d >> 10, kh = (d >> 5) & 31, kw = d & 31;
            int y = lh + kh - PADP, x = lw + kw - PADP;
            if ((unsigned)y < HH && (unsigned)x < WW)
                v = image[(y * WW + x) * CC + c];
        }
        a32[d] = v;
        abf[d] = __float2bfloat16(v);
    }
}

// ---------------- kernel 3: bf16 mma.sync GEMM -> scores ----------------
// CTA 128x128, 256 threads, warps 4(M)x2(N), warp tile 32x64. 4-stage cp.async.
// 2 CTAs/SM: independent barriers keep the tensor pipe fed.
__global__ __launch_bounds__(256, 2) void k_gemm() {
    extern __shared__ char smem[];
    const uint32_t sb = smem_u32(smem);
    const int tid = threadIdx.x, lane = tid & 31, wid = tid >> 5;
    const int wm = (wid & 3) * 32, wn = (wid >> 2) * 64;
    const int rowBase = blockIdx.x * TM, nBase = blockIdx.y * TNB;

    float acc[2][8][4];
#pragma unroll
    for (int mi = 0; mi < 2; ++mi)
#pragma unroll
        for (int nj = 0; nj < 8; ++nj)
#pragma unroll
            for (int q = 0; q < 4; ++q) acc[mi][nj][q] = 0.f;

    // stage loader: A 128x(32 bf16), B 128x(32 bf16); rows padded to 80B
    auto load_stage = [&](int kt) {
        const int slot = kt & 3;
        const uint32_t a0 = sb + slot * STG;
        const uint32_t b0 = a0 + ASTG;
        const int k0 = kt * TK;
#pragma unroll
        for (int i = 0; i < 2; ++i) {   // A: 512 chunks of 16B
            int idx = tid + i * 256;
            int r = idx >> 2, c = idx & 3;
            cp16(a0 + r * AROW + c * 16,
                 (const char*)g_Abf + ((size_t)(rowBase + r) * D_ + k0) * 2 + c * 16);
        }
#pragma unroll
        for (int i = 0; i < 2; ++i) {   // B: 512 chunks of 16B
            int idx = tid + i * 256;
            int r = idx >> 2, c = idx & 3;
            cp16(b0 + r * AROW + c * 16,
                 (const char*)g_Bbf + ((size_t)(nBase + r) * D_ + k0) * 2 + c * 16);
        }
    };

    load_stage(0); cp_commit();
    load_stage(1); cp_commit();
    load_stage(2); cp_commit();

    for (int kt = 0; kt < NKT; ++kt) {
        cp_wait<2>();            // stage kt arrived
        __syncthreads();         // publish; all warps done with stage kt-1's slot
        if (kt + 3 < NKT) load_stage(kt + 3);
        cp_commit();             // uniform group count

        const uint32_t a0 = sb + (kt & 3) * STG;
        const uint32_t b0 = a0 + ASTG;
#pragma unroll
        for (int kh = 0; kh < 2; ++kh) {   // two k16 slices
            uint32_t af[2][4];
#pragma unroll
            for (int mi = 0; mi < 2; ++mi) {
                uint32_t addr = a0 + (wm + mi * 16 + (lane & 15)) * AROW
                              + kh * 32 + ((lane >> 4) & 1) * 16;
                asm volatile("ldmatrix.sync.aligned.m8n8.x4.shared.b16 {%0,%1,%2,%3}, [%4];"
                    : "=r"(af[mi][0]), "=r"(af[mi][1]), "=r"(af[mi][2]), "=r"(af[mi][3])
                    : "r"(addr));
            }
            // B tile n-major (k contiguous): same fragment layout as A (non-trans);
            // r0=(n0-7,kLo) r1=(n8-15,kLo) r2=(n0-7,kHi) r3=(n8-15,kHi)
            uint32_t bfr[8][2];
#pragma unroll
            for (int ni = 0; ni < 4; ++ni) {
                uint32_t r0, r1, r2, r3;
                uint32_t addr = b0 + (wn + ni * 16 + (lane & 15)) * AROW
                              + kh * 32 + ((lane >> 4) & 1) * 16;
                asm volatile("ldmatrix.sync.aligned.m8n8.x4.shared.b16 {%0,%1,%2,%3}, [%4];"
                    : "=r"(r0), "=r"(r1), "=r"(r2), "=r"(r3) : "r"(addr));
                bfr[ni * 2][0]     = r0; bfr[ni * 2][1]     = r2;
                bfr[ni * 2 + 1][0] = r1; bfr[ni * 2 + 1][1] = r3;
            }
#pragma unroll
            for (int mi = 0; mi < 2; ++mi)
#pragma unroll
                for (int nj = 0; nj < 8; ++nj) {
                    asm volatile(
                        "mma.sync.aligned.m16n8k16.row.col.f32.bf16.bf16.f32 "
                        "{%0,%1,%2,%3}, {%4,%5,%6,%7}, {%8,%9}, {%0,%1,%2,%3};"
                        : "+f"(acc[mi][nj][0]), "+f"(acc[mi][nj][1]),
                          "+f"(acc[mi][nj][2]), "+f"(acc[mi][nj][3])
                        : "r"(af[mi][0]), "r"(af[mi][1]), "r"(af[mi][2]), "r"(af[mi][3]),
                          "r"(bfr[nj][0]), "r"(bfr[nj][1]));
                }
        }
    }

    // epilogue: score = acc + bias[n] -> g_scores
#pragma unroll
    for (int mi = 0; mi < 2; ++mi) {
        const int row0 = rowBase + wm + mi * 16 + (lane >> 2);
#pragma unroll
        for (int nj = 0; nj < 8; ++nj) {
            const int col = nBase + wn + nj * 8 + (lane & 3) * 2;
            float2 bv = *(const float2*)(g_bias + col);
            float2 s0 = make_float2(acc[mi][nj][0] + bv.x, acc[mi][nj][1] + bv.y);
            float2 s1 = make_float2(acc[mi][nj][2] + bv.x, acc[mi][nj][3] + bv.y);
            *(float2*)(g_scores + (size_t)row0 * NMEM + col) = s0;
            *(float2*)(g_scores + (size_t)(row0 + 8) * NMEM + col) = s1;
        }
    }
}

// ---------------- kernel 4: scan scores, decide or collect candidates ----------------
__global__ void k_select(const int* __restrict__ mapping) {
    if (blockIdx.x == 0 && threadIdx.x == 0) g_maxkey = 0u;   // reset for fold
    const int l = (blockIdx.x * blockDim.x + threadIdx.x) >> 5;
    const int lane = threadIdx.x & 31;
    if (l >= L_) return;
    const float* row = g_scores + (size_t)l * NMEM;

    float m1 = -3.4e38f, m2 = -3.4e38f;
    int i1 = 0;
    for (int n = lane; n < NMEM; n += 32) {
        float v = row[n];
        if (v > m1) { m2 = m1; m1 = v; i1 = n; }
        else if (v > m2) m2 = v;
    }
#pragma unroll
    for (int off = 16; off; off >>= 1) {
        float om1 = __shfl_xor_sync(0xffffffffu, m1, off);
        float om2 = __shfl_xor_sync(0xffffffffu, m2, off);
        int   oi1 = __shfl_xor_sync(0xffffffffu, i1, off);
        float c2 = fmaxf(fmaxf(m2, om2), fminf(m1, om1));
        if (om1 > m1 || (om1 == m1 && oi1 < i1)) { m1 = om1; i1 = oi1; }
        m2 = c2;
    }

    if (m1 - m2 > MARGIN) {
        if (lane == 0) { g_pid[l] = mapping[i1]; g_candcnt[l] = 1; }
        return;
    }
    // collect candidates within MARGIN of bf16 max (ascending n)
    const float thr = m1 - MARGIN;
    int base = 0;
    for (int n0 = 0; n0 < NMEM; n0 += 32) {
        float v = row[n0 + lane];
        bool p = v >= thr;
        unsigned mask = __ballot_sync(0xffffffffu, p);
        if (p) {
            int pos = base + __popc(mask & ((1u << lane) - 1u));
            if (pos < CMAX) g_cand[(size_t)l * CMAX + pos] = n0 + lane;
        }
        base += __popc(mask);
    }
    if (lane == 0) g_candcnt[l] = base;   // may exceed CMAX -> full rescan
}

// ---------------- kernel 5: exact fp32 rescue for ambiguous patches ----------------
__global__ void k_rescore(const float* __restrict__ mem, const int* __restrict__ mapping) {
    const int l = blockIdx.x;
    const int cnt = g_candcnt[l];
    if (cnt <= 1) return;

    __shared__ float sp[D_];     // 12 KB patch row
    __shared__ float red[4];
    const float* prow = g_Af32 + (size_t)l * D_;
    for (int k = threadIdx.x; k < D_; k += 128) sp[k] = prow[k];
    __syncthreads();

    const bool full = cnt > CMAX;
    const int num = full ? NMEM : cnt;
    float best = -3.4e38f;
    int bestn = 0;
    for (int c = 0; c < num; ++c) {
        const int n = full ? c : g_cand[(size_t)l * CMAX + c];
        const float* mrow = mem + (size_t)n * D_;
        float s = 0.f;
        for (int k = threadIdx.x; k < D_; k += 128) s = fmaf(sp[k], mrow[k], s);
#pragma unroll
        for (int o = 16; o; o >>= 1) s += __shfl_xor_sync(0xffffffffu, s, o);
        if ((threadIdx.x & 31) == 0) red[threadIdx.x >> 5] = s;
        __syncthreads();
        if (threadIdx.x == 0) {
            float tot = red[0] + red[1] + red[2] + red[3] + g_bias[n];
            if (tot > best) { best = tot; bestn = n; }   // ascending n -> first max wins
        }
        __syncthreads();
    }
    if (threadIdx.x == 0) g_pid[l] = mapping[bestn];
}

// ---------------- kernel 6: fold (gather) + global max ----------------
__global__ void k_fold(const float* __restrict__ mem2) {
    __shared__ int spid[32 * LWW];
    const int h = blockIdx.x;
    const int c = blockIdx.y;
    const int w = threadIdx.x;               // 0..127

    const int lh0 = max(0, h - (KHH - 1 - PADP));
    const int lh1 = min(LHH - 1, h + PADP);
    const int nrows = lh1 - lh0 + 1;
    for (int idx = threadIdx.x; idx < nrows * LWW; idx += 128)
        spid[idx] = g_pid[(lh0 + idx / LWW) * LWW + idx % LWW];
    __syncthreads();

    float s = 0.f;
#pragma unroll 1
    for (int kh = 0; kh < KHH; ++kh) {
        int lh = h + PADP - kh;
        if (lh < lh0 || lh > lh1) continue;
        const int base = (lh - lh0) * LWW;
        const int rowoff = c * 1024 + kh * 32;
#pragma unroll
        for (int kw = 0; kw < KWW; ++kw) {
            int lw = w + PADP - kw;
            if ((unsigned)lw < LWW) {
                int pid = spid[base + lw];
                s += __ldg(&mem2[(size_t)pid * D_ + rowoff + kw]);
            }
        }
    }
    g_facc[(c * HH + h) * WW + w] = s;

    float m = s;
#pragma unroll
    for (int o = 16; o; o >>= 1) m = fmaxf(m, __shfl_xor_sync(0xffffffffu, m, o));
    __shared__ float wm[4];
    if ((threadIdx.x & 31) == 0) wm[threadIdx.x >> 5] = m;
    __syncthreads();
    if (threadIdx.x == 0) {
        m = fmaxf(fmaxf(wm[0], wm[1]), fmaxf(wm[2], wm[3]));
        unsigned b = __float_as_uint(m);
        unsigned key = (b & 0x80000000u) ? ~b : (b | 0x80000000u);
        atomicMax(&g_maxkey, key);
    }
}

// ---------------- kernel 7: normalize + transpose to (H,W,C) ----------------
__global__ void k_norm(float* __restrict__ out) {
    int i = blockIdx.x * 256 + threadIdx.x;
    if (i >= HH * WW * CC) return;
    unsigned key = g_maxkey;
    unsigned b = (key & 0x80000000u) ? (key & 0x7fffffffu) : ~key;
    float mx = __uint_as_float(b);
    int c = i % CC;
    int w = (i / CC) % WW;
    int h = i / (CC * WW);
    out[i] = g_facc[(c * HH + h) * WW + w] / mx;
}

// ---------------- launcher ----------------
extern "C" void kernel_launch(void* const* d_in, const int* in_sizes, int n_in,
                              void* d_out, int out_size) {
    const float* image   = (const float*)d_in[0];
    const float* mem     = (const float*)d_in[1];
    const float* mem2    = (const float*)d_in[2];
    const int*   mapping = (const int*)d_in[3];
    float* out = (float*)d_out;

    cudaFuncSetAttribute(k_gemm, cudaFuncAttributeMaxDynamicSharedMemorySize, SMEM_GEMM);

    k_prepB<<<NMEM, 128>>>(mem);
    k_im2colA<<<LPAD, 256>>>(image);
    k_gemm<<<dim3(LPAD / TM, NMEM / TNB), 256, SMEM_GEMM>>>();
    k_select<<<(L_ + 7) / 8, 256>>>(mapping);
    k_rescore<<<L_, 128>>>(mem, mapping);
    k_fold<<<dim3(HH, CC), 128>>>(mem2);
    k_norm<<<(HH * WW * CC + 255) / 256, 256>>>(out);
}

// round 9
// speedup vs baseline: 5.1906x; 1.1172x over previous
#include <cuda_runtime.h>
#include <cuda_bf16.h>
#include <cstdint>

// ---------------- problem constants ----------------
#define L_      13689           // LH*LW
#define LPAD    13696           // 107 * 128
#define D_      3072            // C*KH*KW
#define NMEM    4096
#define HH      128
#define WW      128
#define CC      3
#define KHH     32
#define KWW     32
#define PADP    10
#define LHH     117
#define LWW     117

// ---------------- GEMM tiling (mma.sync bf16, m16n8k16) ----------------
#define TM      128              // CTA M
#define TNB     128              // CTA N
#define TK      64               // K per stage (two k32 halves, 4 k16 slices)
#define NKT     (D_ / TK)        // 48
#define AROW    144              // bytes per smem row: 64 bf16 (128B) + 16B pad
#define ASTG    (TM * AROW)      // 18432
#define BSTG    (TNB * AROW)     // 18432
#define STG     (ASTG + BSTG)    // 36864
#define SMEM_GEMM (3 * STG)      // 110592 (3 stages) -> 2 CTAs/SM (216KB/228KB)

#define MARGIN  2.0f
#define CMAX    16

typedef unsigned long long ull;

// ---------------- static device scratch ----------------
__device__ __align__(16) __nv_bfloat16 g_Abf [(size_t)LPAD * D_];   // 84 MB
__device__ __align__(16) __nv_bfloat16 g_Bbf [(size_t)NMEM * D_];   // 25 MB
__device__ __align__(16) float         g_bias[NMEM];                // -0.5*||mem_n||^2 exact
__device__ __align__(16) float         g_scores[(size_t)LPAD * NMEM]; // 224 MB
__device__ int   g_cand[(size_t)L_ * CMAX];
__device__ int   g_candcnt[L_];
__device__ int   g_pid[L_];
__device__ float g_facc[CC * HH * WW];
__device__ unsigned int g_maxkey;

// ---------------- helpers ----------------
__device__ __forceinline__ uint32_t smem_u32(const void* p) {
    uint32_t a;
    asm("{ .reg .u64 t; cvta.to.shared.u64 t, %1; cvt.u32.u64 %0, t; }" : "=r"(a) : "l"(p));
    return a;
}
__device__ __forceinline__ void cp16(uint32_t smem_dst, const void* gsrc) {
    asm volatile("cp.async.cg.shared.global [%0], [%1], 16;" :: "r"(smem_dst), "l"(gsrc));
}
__device__ __forceinline__ void cp_commit() { asm volatile("cp.async.commit_group;"); }
template <int N> __device__ __forceinline__ void cp_wait() {
    asm volatile("cp.async.wait_group %0;" :: "n"(N));
}

// ---------------- kernel 1: bias (exact fp32) + mem -> bf16 ----------------
__global__ void k_prepB(const float* __restrict__ mem) {
    int row = blockIdx.x;
    const float* r = mem + (size_t)row * D_;
    __nv_bfloat16* b = g_Bbf + (size_t)row * D_;
    float s = 0.f;
    for (int i = threadIdx.x; i < D_; i += 128) {
        float v = r[i];
        b[i] = __float2bfloat16(v);
        s += v * v;
    }
#pragma unroll
    for (int o = 16; o; o >>= 1) s += __shfl_xor_sync(0xffffffffu, s, o);
    __shared__ float ws[4];
    if ((threadIdx.x & 31) == 0) ws[threadIdx.x >> 5] = s;
    __syncthreads();
    if (threadIdx.x == 0) g_bias[row] = -0.5f * (ws[0] + ws[1] + ws[2] + ws[3]);
}

// ---------------- kernel 2: im2col -> bf16 only, layout [l][d] ----------------
__global__ void k_im2colA(const float* __restrict__ image) {
    const int l = blockIdx.x;                  // 0..LPAD-1
    const bool valid = l < L_;
    const int lh = l / LWW, lw = l - lh * LWW;
    __nv_bfloat16* abf = g_Abf + (size_t)l * D_;
    for (int d = threadIdx.x; d < D_; d += 256) {
        float v = 0.f;
        if (valid) {
            int c = d >> 10, kh = (d >> 5) & 31, kw = d & 31;
            int y = lh + kh - PADP, x = lw + kw - PADP;
            if ((unsigned)y < HH && (unsigned)x < WW)
                v = image[(y * WW + x) * CC + c];
        }
        abf[d] = __float2bfloat16(v);
    }
}

// ---------------- kernel 3: bf16 mma.sync GEMM -> scores ----------------
// CTA 128x128, 256 threads, warps 4(M)x2(N), warp tile 32x64.
// TK=64 per stage, 3 stages -> 48 barrier rounds. 2 CTAs/SM.
__global__ __launch_bounds__(256, 2) void k_gemm() {
    extern __shared__ char smem[];
    const uint32_t sb = smem_u32(smem);
    const int tid = threadIdx.x, lane = tid & 31, wid = tid >> 5;
    const int wm = (wid & 3) * 32, wn = (wid >> 2) * 64;
    const int rowBase = blockIdx.x * TM, nBase = blockIdx.y * TNB;

    float acc[2][8][4];
#pragma unroll
    for (int mi = 0; mi < 2; ++mi)
#pragma unroll
        for (int nj = 0; nj < 8; ++nj)
#pragma unroll
            for (int q = 0; q < 4; ++q) acc[mi][nj][q] = 0.f;

    // stage loader: A 128x(64 bf16), B 128x(64 bf16); rows padded to 144B
    auto load_stage = [&](int kt) {
        const int slot = kt % 3;
        const uint32_t a0 = sb + slot * STG;
        const uint32_t b0 = a0 + ASTG;
        const int k0 = kt * TK;
#pragma unroll
        for (int i = 0; i < 4; ++i) {   // A: 1024 chunks of 16B
            int idx = tid + i * 256;
            int r = idx >> 3, c = idx & 7;
            cp16(a0 + r * AROW + c * 16,
                 (const char*)g_Abf + ((size_t)(rowBase + r) * D_ + k0) * 2 + c * 16);
        }
#pragma unroll
        for (int i = 0; i < 4; ++i) {   // B: 1024 chunks of 16B
            int idx = tid + i * 256;
            int r = idx >> 3, c = idx & 7;
            cp16(b0 + r * AROW + c * 16,
                 (const char*)g_Bbf + ((size_t)(nBase + r) * D_ + k0) * 2 + c * 16);
        }
    };

    load_stage(0); cp_commit();
    load_stage(1); cp_commit();

    for (int kt = 0; kt < NKT; ++kt) {
        cp_wait<1>();            // stage kt arrived (kt+1 may still fly)
        __syncthreads();         // publish; all warps done with slot (kt+2)%3's old stage
        if (kt + 2 < NKT) load_stage(kt + 2);
        cp_commit();             // uniform group count

        const uint32_t a0 = sb + (kt % 3) * STG;
        const uint32_t b0 = a0 + ASTG;
#pragma unroll
        for (int kh = 0; kh < 4; ++kh) {   // four k16 slices
            uint32_t af[2][4];
#pragma unroll
            for (int mi = 0; mi < 2; ++mi) {
                uint32_t addr = a0 + (wm + mi * 16 + (lane & 15)) * AROW
                              + kh * 32 + ((lane >> 4) & 1) * 16;
                asm volatile("ldmatrix.sync.aligned.m8n8.x4.shared.b16 {%0,%1,%2,%3}, [%4];"
                    : "=r"(af[mi][0]), "=r"(af[mi][1]), "=r"(af[mi][2]), "=r"(af[mi][3])
                    : "r"(addr));
            }
            // B tile n-major (k contiguous): same fragment layout as A (non-trans);
            // r0=(n0-7,kLo) r1=(n8-15,kLo) r2=(n0-7,kHi) r3=(n8-15,kHi)
            uint32_t bfr[8][2];
#pragma unroll
            for (int ni = 0; ni < 4; ++ni) {
                uint32_t r0, r1, r2, r3;
                uint32_t addr = b0 + (wn + ni * 16 + (lane & 15)) * AROW
                              + kh * 32 + ((lane >> 4) & 1) * 16;
                asm volatile("ldmatrix.sync.aligned.m8n8.x4.shared.b16 {%0,%1,%2,%3}, [%4];"
                    : "=r"(r0), "=r"(r1), "=r"(r2), "=r"(r3) : "r"(addr));
                bfr[ni * 2][0]     = r0; bfr[ni * 2][1]     = r2;
                bfr[ni * 2 + 1][0] = r1; bfr[ni * 2 + 1][1] = r3;
            }
#pragma unroll
            for (int mi = 0; mi < 2; ++mi)
#pragma unroll
                for (int nj = 0; nj < 8; ++nj) {
                    asm volatile(
                        "mma.sync.aligned.m16n8k16.row.col.f32.bf16.bf16.f32 "
                        "{%0,%1,%2,%3}, {%4,%5,%6,%7}, {%8,%9}, {%0,%1,%2,%3};"
                        : "+f"(acc[mi][nj][0]), "+f"(acc[mi][nj][1]),
                          "+f"(acc[mi][nj][2]), "+f"(acc[mi][nj][3])
                        : "r"(af[mi][0]), "r"(af[mi][1]), "r"(af[mi][2]), "r"(af[mi][3]),
                          "r"(bfr[nj][0]), "r"(bfr[nj][1]));
                }
        }
    }

    // epilogue: score = acc + bias[n] -> g_scores
#pragma unroll
    for (int mi = 0; mi < 2; ++mi) {
        const int row0 = rowBase + wm + mi * 16 + (lane >> 2);
#pragma unroll
        for (int nj = 0; nj < 8; ++nj) {
            const int col = nBase + wn + nj * 8 + (lane & 3) * 2;
            float2 bv = *(const float2*)(g_bias + col);
            float2 s0 = make_float2(acc[mi][nj][0] + bv.x, acc[mi][nj][1] + bv.y);
            float2 s1 = make_float2(acc[mi][nj][2] + bv.x, acc[mi][nj][3] + bv.y);
            *(float2*)(g_scores + (size_t)row0 * NMEM + col) = s0;
            *(float2*)(g_scores + (size_t)(row0 + 8) * NMEM + col) = s1;
        }
    }
}

// ---------------- kernel 4: scan scores, decide or collect candidates ----------------
__global__ void k_select(const int* __restrict__ mapping) {
    if (blockIdx.x == 0 && threadIdx.x == 0) g_maxkey = 0u;   // reset for fold
    const int l = (blockIdx.x * blockDim.x + threadIdx.x) >> 5;
    const int lane = threadIdx.x & 31;
    if (l >= L_) return;
    const float* row = g_scores + (size_t)l * NMEM;

    // pass 1: vectorized top1/top2; each lane scans 4 consecutive n (ascending)
    float m1 = -3.4e38f, m2 = -3.4e38f;
    int i1 = 0;
    for (int n0 = lane * 4; n0 < NMEM; n0 += 128) {
        float4 v = *(const float4*)(row + n0);
        if (v.x > m1) { m2 = m1; m1 = v.x; i1 = n0; }     else if (v.x > m2) m2 = v.x;
        if (v.y > m1) { m2 = m1; m1 = v.y; i1 = n0 + 1; } else if (v.y > m2) m2 = v.y;
        if (v.z > m1) { m2 = m1; m1 = v.z; i1 = n0 + 2; } else if (v.z > m2) m2 = v.z;
        if (v.w > m1) { m2 = m1; m1 = v.w; i1 = n0 + 3; } else if (v.w > m2) m2 = v.w;
    }
#pragma unroll
    for (int off = 16; off; off >>= 1) {
        float om1 = __shfl_xor_sync(0xffffffffu, m1, off);
        float om2 = __shfl_xor_sync(0xffffffffu, m2, off);
        int   oi1 = __shfl_xor_sync(0xffffffffu, i1, off);
        float c2 = fmaxf(fmaxf(m2, om2), fminf(m1, om1));
        if (om1 > m1 || (om1 == m1 && oi1 < i1)) { m1 = om1; i1 = oi1; }
        m2 = c2;
    }

    if (m1 - m2 > MARGIN) {
        if (lane == 0) { g_pid[l] = mapping[i1]; g_candcnt[l] = 1; }
        return;
    }
    // collect candidates within MARGIN of bf16 max (ascending n)
    const float thr = m1 - MARGIN;
    int base = 0;
    for (int n0 = 0; n0 < NMEM; n0 += 32) {
        float v = row[n0 + lane];
        bool p = v >= thr;
        unsigned mask = __ballot_sync(0xffffffffu, p);
        if (p) {
            int pos = base + __popc(mask & ((1u << lane) - 1u));
            if (pos < CMAX) g_cand[(size_t)l * CMAX + pos] = n0 + lane;
        }
        base += __popc(mask);
    }
    if (lane == 0) g_candcnt[l] = base;   // may exceed CMAX -> full rescan
}

// ---------------- kernel 5: exact fp32 rescue for ambiguous patches ----------------
// Patch rebuilt exactly from image (same indexing as im2col, fp32).
__global__ void k_rescore(const float* __restrict__ image,
                          const float* __restrict__ mem,
                          const int* __restrict__ mapping) {
    const int l = blockIdx.x;
    const int cnt = g_candcnt[l];
    if (cnt <= 1) return;

    __shared__ float sp[D_];     // 12 KB patch row
    __shared__ float red[4];
    const int lh = l / LWW, lw = l - lh * LWW;
    for (int d = threadIdx.x; d < D_; d += 128) {
        int c = d >> 10, kh = (d >> 5) & 31, kw = d & 31;
        int y = lh + kh - PADP, x = lw + kw - PADP;
        float v = 0.f;
        if ((unsigned)y < HH && (unsigned)x < WW)
            v = image[(y * WW + x) * CC + c];
        sp[d] = v;
    }
    __syncthreads();

    const bool full = cnt > CMAX;
    const int num = full ? NMEM : cnt;
    float best = -3.4e38f;
    int bestn = 0;
    for (int c = 0; c < num; ++c) {
        const int n = full ? c : g_cand[(size_t)l * CMAX + c];
        const float* mrow = mem + (size_t)n * D_;
        float s = 0.f;
        for (int k = threadIdx.x; k < D_; k += 128) s = fmaf(sp[k], mrow[k], s);
#pragma unroll
        for (int o = 16; o; o >>= 1) s += __shfl_xor_sync(0xffffffffu, s, o);
        if ((threadIdx.x & 31) == 0) red[threadIdx.x >> 5] = s;
        __syncthreads();
        if (threadIdx.x == 0) {
            float tot = red[0] + red[1] + red[2] + red[3] + g_bias[n];
            if (tot > best) { best = tot; bestn = n; }   // ascending n -> first max wins
        }
        __syncthreads();
    }
    if (threadIdx.x == 0) g_pid[l] = mapping[bestn];
}

// ---------------- kernel 6: fold (gather) + global max ----------------
__global__ void k_fold(const float* __restrict__ mem2) {
    __shared__ int spid[32 * LWW];
    const int h = blockIdx.x;
    const int c = blockIdx.y;
    const int w = threadIdx.x;               // 0..127

    const int lh0 = max(0, h - (KHH - 1 - PADP));
    const int lh1 = min(LHH - 1, h + PADP);
    const int nrows = lh1 - lh0 + 1;
    for (int idx = threadIdx.x; idx < nrows * LWW; idx += 128)
        spid[idx] = g_pid[(lh0 + idx / LWW) * LWW + idx % LWW];
    __syncthreads();

    float s = 0.f;
#pragma unroll 1
    for (int kh = 0; kh < KHH; ++kh) {
        int lh = h + PADP - kh;
        if (lh < lh0 || lh > lh1) continue;
        const int base = (lh - lh0) * LWW;
        const int rowoff = c * 1024 + kh * 32;
#pragma unroll
        for (int kw = 0; kw < KWW; ++kw) {
            int lw = w + PADP - kw;
            if ((unsigned)lw < LWW) {
                int pid = spid[base + lw];
                s += __ldg(&mem2[(size_t)pid * D_ + rowoff + kw]);
            }
        }
    }
    g_facc[(c * HH + h) * WW + w] = s;

    float m = s;
#pragma unroll
    for (int o = 16; o; o >>= 1) m = fmaxf(m, __shfl_xor_sync(0xffffffffu, m, o));
    __shared__ float wm[4];
    if ((threadIdx.x & 31) == 0) wm[threadIdx.x >> 5] = m;
    __syncthreads();
    if (threadIdx.x == 0) {
        m = fmaxf(fmaxf(wm[0], wm[1]), fmaxf(wm[2], wm[3]));
        unsigned b = __float_as_uint(m);
        unsigned key = (b & 0x80000000u) ? ~b : (b | 0x80000000u);
        atomicMax(&g_maxkey, key);
    }
}

// ---------------- kernel 7: normalize + transpose to (H,W,C) ----------------
__global__ void k_norm(float* __restrict__ out) {
    int i = blockIdx.x * 256 + threadIdx.x;
    if (i >= HH * WW * CC) return;
    unsigned key = g_maxkey;
    unsigned b = (key & 0x80000000u) ? (key & 0x7fffffffu) : ~key;
    float mx = __uint_as_float(b);
    int c = i % CC;
    int w = (i / CC) % WW;
    int h = i / (CC * WW);
    out[i] = g_facc[(c * HH + h) * WW + w] / mx;
}

// ---------------- launcher ----------------
extern "C" void kernel_launch(void* const* d_in, const int* in_sizes, int n_in,
                              void* d_out, int out_size) {
    const float* image   = (const float*)d_in[0];
    const float* mem     = (const float*)d_in[1];
    const float* mem2    = (const float*)d_in[2];
    const int*   mapping = (const int*)d_in[3];
    float* out = (float*)d_out;

    cudaFuncSetAttribute(k_gemm, cudaFuncAttributeMaxDynamicSharedMemorySize, SMEM_GEMM);

    k_prepB<<<NMEM, 128>>>(mem);
    k_im2colA<<<LPAD, 256>>>(image);
    k_gemm<<<dim3(LPAD / TM, NMEM / TNB), 256, SMEM_GEMM>>>();
    k_select<<<(L_ + 7) / 8, 256>>>(mapping);
    k_rescore<<<L_, 128>>>(image, mem, mapping);
    k_fold<<<dim3(HH, CC), 128>>>(mem2);
    k_norm<<<(HH * WW * CC + 255) / 256, 256>>>(out);
}